// round 15
// baseline (speedup 1.0000x reference)
#include <cuda_runtime.h>
#include <cstdint>

// DipolePredictorE3NN — R15: raise CTA residency. Feats via TMA (14.3KB smem),
// coors via LDG.128 to registers (overlaps TMA; saves 6KB smem -> ~15 CTAs/SM
// resident vs ~11). Per-SM in-flight-bytes model says residency ~ bandwidth.
//   d_in[0] feats [B,N,7] f32 | d_in[1] coors [B,N,3] f32 | d_in[2] adj (UNUSED)
//   d_in[3] W_tp[7] | d_in[4] W1[128,3] | d_in[5] b1[128] | d_in[6] W2[3,128] | d_in[7] b2[3]
// Output: [B,3] f32

#define NS 7
#define HID 128
#define THREADS 128
#define N_FIXED 512
#define FEATS_BYTES (N_FIXED * NS * 4)   // 14336

__device__ __forceinline__ uint32_t smem_u32(const void* p) {
    uint32_t a;
    asm("{ .reg .u64 t; cvta.to.shared.u64 t, %1; cvt.u32.u64 %0, t; }"
        : "=r"(a) : "l"(p));
    return a;
}

__device__ __forceinline__ void mbar_wait0(uint32_t mbar) {
    uint32_t done;
    asm volatile(
        "{ .reg .pred p; mbarrier.try_wait.parity.shared.b64 p, [%1], 0; "
        "selp.b32 %0, 1, 0, p; }"
        : "=r"(done) : "r"(mbar) : "memory");
    if (!done) {
        asm volatile(
            "{ .reg .pred P1;\n"
            "W_%=: mbarrier.try_wait.parity.shared.b64 P1, [%0], 0, 0x989680;\n"
            "@P1 bra.uni D_%=;\n"
            "bra.uni W_%=;\n"
            "D_%=: }"
            :: "r"(mbar) : "memory");
    }
}

// ---------- fast path: N==512 ----------
__global__ __launch_bounds__(THREADS, 12)
void dipole_r15_kernel(const float* __restrict__ feats,
                       const float* __restrict__ coors,
                       const float* __restrict__ W_tp,
                       const float* __restrict__ W1,
                       const float* __restrict__ b1,
                       const float* __restrict__ W2,
                       const float* __restrict__ b2,
                       float* __restrict__ out)
{
    __shared__ __align__(16) float s_feats[N_FIXED * NS];  // 14336 B
    __shared__ __align__(8)  uint64_t s_mbar;
    __shared__ float sx[4], sy[4], sz[4];

    const int b    = blockIdx.x;
    const int tid  = threadIdx.x;
    const int lane = tid & 31;
    const int wid  = tid >> 5;

    const uint32_t mbar = smem_u32(&s_mbar);

    if (tid == 0) {
        asm volatile("mbarrier.init.shared.b64 [%0], 1;" :: "r"(mbar) : "memory");
    }
    __syncthreads();

    if (tid == 0) {
        asm volatile("mbarrier.arrive.expect_tx.shared.b64 _, [%0], %1;"
                     :: "r"(mbar), "r"((uint32_t)FEATS_BYTES) : "memory");
        const char* gf = (const char*)(feats + (size_t)b * N_FIXED * NS);
        asm volatile(
            "cp.async.bulk.shared::cta.global.mbarrier::complete_tx::bytes "
            "[%0], [%1], %2, [%3];"
            :: "r"(smem_u32(s_feats)), "l"(gf), "r"((uint32_t)FEATS_BYTES),
               "r"(mbar) : "memory");
    }

    // While the feats TMA streams: coors via LDG.128 into registers (uses the
    // otherwise-idle LSU/L1 path for 30% of the bytes) + TP weights.
    float4 cc4[3];
    {
        const float4* c4 = reinterpret_cast<const float4*>(
            coors + (size_t)b * N_FIXED * 3) + tid * 3;
#pragma unroll
        for (int i = 0; i < 3; i++) cc4[i] = __ldg(&c4[i]);
    }
    const float* cc = reinterpret_cast<const float*>(cc4);

    float w[NS];
#pragma unroll
    for (int i = 0; i < NS; i++) w[i] = __ldg(&W_tp[i]);

    mbar_wait0(mbar);

    // Thread tid owns 4 consecutive nodes; feats from conflict-free smem.
    float ax = 0.f, ay = 0.f, az = 0.f;
    {
        const float4* f4 = reinterpret_cast<const float4*>(s_feats) + tid * 7;
        float4 ff4[7];
#pragma unroll
        for (int i = 0; i < 7; i++) ff4[i] = f4[i];
        const float* ff = reinterpret_cast<const float*>(ff4);
#pragma unroll
        for (int j = 0; j < 4; j++) {
            float s = 0.f;
#pragma unroll
            for (int i = 0; i < NS; i++) s = fmaf(ff[j * NS + i], w[i], s);
            ax = fmaf(s, cc[j * 3 + 0], ax);
            ay = fmaf(s, cc[j * 3 + 1], ay);
            az = fmaf(s, cc[j * 3 + 2], az);
        }
    }

#pragma unroll
    for (int o = 16; o > 0; o >>= 1) {
        ax += __shfl_down_sync(0xFFFFFFFFu, ax, o);
        ay += __shfl_down_sync(0xFFFFFFFFu, ay, o);
        az += __shfl_down_sync(0xFFFFFFFFu, az, o);
    }
    if (lane == 0) { sx[wid] = ax; sy[wid] = ay; sz[wid] = az; }
    __syncthreads();

    if (wid == 0) {
        float rx = (lane < 4) ? sx[lane] : 0.f;
        float ry = (lane < 4) ? sy[lane] : 0.f;
        float rz = (lane < 4) ? sz[lane] : 0.f;
#pragma unroll
        for (int o = 2; o > 0; o >>= 1) {
            rx += __shfl_down_sync(0xFFFFFFFFu, rx, o);
            ry += __shfl_down_sync(0xFFFFFFFFu, ry, o);
            rz += __shfl_down_sync(0xFFFFFFFFu, rz, o);
        }
        const float scale = 0.3779644730092272f / (float)N_FIXED;  // 1/sqrt(7)/N
        float g0 = __shfl_sync(0xFFFFFFFFu, rx, 0) * scale;
        float g1 = __shfl_sync(0xFFFFFFFFu, ry, 0) * scale;
        float g2 = __shfl_sync(0xFFFFFFFFu, rz, 0) * scale;

        // MLP: out = W2 @ relu(W1 @ g + b1) + b2 ; each lane owns 4 hidden units.
        float o0 = 0.f, o1 = 0.f, o2 = 0.f;
#pragma unroll
        for (int r = 0; r < HID / 32; r++) {
            int j = lane + r * 32;
            float h = fmaf(W1[j * 3 + 0], g0,
                      fmaf(W1[j * 3 + 1], g1,
                      fmaf(W1[j * 3 + 2], g2, b1[j])));
            h = fmaxf(h, 0.f);
            o0 = fmaf(W2[0 * HID + j], h, o0);
            o1 = fmaf(W2[1 * HID + j], h, o1);
            o2 = fmaf(W2[2 * HID + j], h, o2);
        }
#pragma unroll
        for (int o = 16; o > 0; o >>= 1) {
            o0 += __shfl_down_sync(0xFFFFFFFFu, o0, o);
            o1 += __shfl_down_sync(0xFFFFFFFFu, o1, o);
            o2 += __shfl_down_sync(0xFFFFFFFFu, o2, o);
        }
        if (lane == 0) {
            out[b * 3 + 0] = o0 + b2[0];
            out[b * 3 + 1] = o1 + b2[1];
            out[b * 3 + 2] = o2 + b2[2];
        }
    }
}

// ---------- generic fallback (any N) ----------
__global__ __launch_bounds__(THREADS)
void dipole_ldg_kernel(const float* __restrict__ feats,
                       const float* __restrict__ coors,
                       const float* __restrict__ W_tp,
                       const float* __restrict__ W1,
                       const float* __restrict__ b1,
                       const float* __restrict__ W2,
                       const float* __restrict__ b2,
                       float* __restrict__ out,
                       int N)
{
    const int b    = blockIdx.x;
    const int tid  = threadIdx.x;
    const int lane = tid & 31;
    const int wid  = tid >> 5;
    float w[NS];
#pragma unroll
    for (int i = 0; i < NS; i++) w[i] = __ldg(&W_tp[i]);
    const float* fb = feats + (size_t)b * N * NS;
    const float* cb = coors + (size_t)b * N * 3;
    float ax = 0.f, ay = 0.f, az = 0.f;
    for (int n = tid; n < N; n += THREADS) {
        const float* fr = fb + (size_t)n * NS;
        float s = 0.f;
#pragma unroll
        for (int i = 0; i < NS; i++) s = fmaf(fr[i], w[i], s);
        const float* cr = cb + (size_t)n * 3;
        ax = fmaf(s, cr[0], ax);
        ay = fmaf(s, cr[1], ay);
        az = fmaf(s, cr[2], az);
    }
#pragma unroll
    for (int o = 16; o > 0; o >>= 1) {
        ax += __shfl_down_sync(0xFFFFFFFFu, ax, o);
        ay += __shfl_down_sync(0xFFFFFFFFu, ay, o);
        az += __shfl_down_sync(0xFFFFFFFFu, az, o);
    }
    __shared__ float sx[4], sy[4], sz[4];
    if (lane == 0) { sx[wid] = ax; sy[wid] = ay; sz[wid] = az; }
    __syncthreads();
    if (wid == 0) {
        float rx = (lane < 4) ? sx[lane] : 0.f;
        float ry = (lane < 4) ? sy[lane] : 0.f;
        float rz = (lane < 4) ? sz[lane] : 0.f;
#pragma unroll
        for (int o = 2; o > 0; o >>= 1) {
            rx += __shfl_down_sync(0xFFFFFFFFu, rx, o);
            ry += __shfl_down_sync(0xFFFFFFFFu, ry, o);
            rz += __shfl_down_sync(0xFFFFFFFFu, rz, o);
        }
        const float scale = 0.3779644730092272f / (float)N;
        float g0 = __shfl_sync(0xFFFFFFFFu, rx, 0) * scale;
        float g1 = __shfl_sync(0xFFFFFFFFu, ry, 0) * scale;
        float g2 = __shfl_sync(0xFFFFFFFFu, rz, 0) * scale;
        float o0 = 0.f, o1 = 0.f, o2 = 0.f;
#pragma unroll
        for (int r = 0; r < HID / 32; r++) {
            int j = lane + r * 32;
            float h = fmaf(W1[j * 3 + 0], g0,
                      fmaf(W1[j * 3 + 1], g1,
                      fmaf(W1[j * 3 + 2], g2, b1[j])));
            h = fmaxf(h, 0.f);
            o0 = fmaf(W2[0 * HID + j], h, o0);
            o1 = fmaf(W2[1 * HID + j], h, o1);
            o2 = fmaf(W2[2 * HID + j], h, o2);
        }
#pragma unroll
        for (int o = 16; o > 0; o >>= 1) {
            o0 += __shfl_down_sync(0xFFFFFFFFu, o0, o);
            o1 += __shfl_down_sync(0xFFFFFFFFu, o1, o);
            o2 += __shfl_down_sync(0xFFFFFFFFu, o2, o);
        }
        if (lane == 0) {
            out[b * 3 + 0] = o0 + b2[0];
            out[b * 3 + 1] = o1 + b2[1];
            out[b * 3 + 2] = o2 + b2[2];
        }
    }
}

extern "C" void kernel_launch(void* const* d_in, const int* in_sizes, int n_in,
                              void* d_out, int out_size)
{
    const float* feats = (const float*)d_in[0];
    const float* coors = (const float*)d_in[1];
    // d_in[2] = adj_mat, intentionally unused
    const float* W_tp  = (const float*)d_in[3];
    const float* W1    = (const float*)d_in[4];
    const float* b1    = (const float*)d_in[5];
    const float* W2    = (const float*)d_in[6];
    const float* b2    = (const float*)d_in[7];
    float* out = (float*)d_out;

    const int B = out_size / 3;           // output [B,3]
    const int N = in_sizes[1] / (B * 3);  // coors [B,N,3]

    if (N == N_FIXED) {
        dipole_r15_kernel<<<B, THREADS>>>(feats, coors, W_tp, W1, b1, W2, b2, out);
    } else {
        dipole_ldg_kernel<<<B, THREADS>>>(feats, coors, W_tp, W1, b1, W2, b2, out, N);
    }
}

// round 16
// speedup vs baseline: 1.0198x; 1.0198x over previous
#include <cuda_runtime.h>
#include <cstdint>

// DipolePredictorE3NN — FINAL (R16 = R14 verbatim, the measured champion:
// 7.584us). Structure: both tiles via cp.async.bulk (TMA), single mbarrier,
// compute from smem, short epilogue. 15 rounds established an environment-
// level ~2.6TB/s memory ceiling binding all transports (LDG any width, TMA,
// hybrids, evict_last, residency changes); 21MB single-pass read => ~7.6-8us
// floor, and this variant owns the best samples of it. R15's hybrid
// (LDG coors alongside TMA) regressed -> keep ALL bytes on the TMA path.
//   d_in[0] feats [B,N,7] f32 | d_in[1] coors [B,N,3] f32 | d_in[2] adj (UNUSED)
//   d_in[3] W_tp[7] | d_in[4] W1[128,3] | d_in[5] b1[128] | d_in[6] W2[3,128] | d_in[7] b2[3]
// Output: [B,3] f32

#define NS 7
#define HID 128
#define THREADS 128
#define N_FIXED 512
#define FEATS_BYTES (N_FIXED * NS * 4)   // 14336
#define COORS_BYTES (N_FIXED * 3 * 4)    // 6144

__device__ __forceinline__ uint32_t smem_u32(const void* p) {
    uint32_t a;
    asm("{ .reg .u64 t; cvta.to.shared.u64 t, %1; cvt.u32.u64 %0, t; }"
        : "=r"(a) : "l"(p));
    return a;
}

__device__ __forceinline__ void mbar_wait0(uint32_t mbar) {
    uint32_t done;
    asm volatile(
        "{ .reg .pred p; mbarrier.try_wait.parity.shared.b64 p, [%1], 0; "
        "selp.b32 %0, 1, 0, p; }"
        : "=r"(done) : "r"(mbar) : "memory");
    if (!done) {
        asm volatile(
            "{ .reg .pred P1;\n"
            "W_%=: mbarrier.try_wait.parity.shared.b64 P1, [%0], 0, 0x989680;\n"
            "@P1 bra.uni D_%=;\n"
            "bra.uni W_%=;\n"
            "D_%=: }"
            :: "r"(mbar) : "memory");
    }
}

// ---------- fast path: N==512 ----------
__global__ __launch_bounds__(THREADS, 8)
void dipole_final_kernel(const float* __restrict__ feats,
                         const float* __restrict__ coors,
                         const float* __restrict__ W_tp,
                         const float* __restrict__ W1,
                         const float* __restrict__ b1,
                         const float* __restrict__ W2,
                         const float* __restrict__ b2,
                         float* __restrict__ out)
{
    __shared__ __align__(16) float s_feats[N_FIXED * NS];  // 14336 B
    __shared__ __align__(16) float s_coors[N_FIXED * 3];   // 6144 B
    __shared__ __align__(8)  uint64_t s_mbar;
    __shared__ float sx[4], sy[4], sz[4];

    const int b    = blockIdx.x;
    const int tid  = threadIdx.x;
    const int lane = tid & 31;
    const int wid  = tid >> 5;

    const uint32_t mbar = smem_u32(&s_mbar);

    if (tid == 0) {
        asm volatile("mbarrier.init.shared.b64 [%0], 1;" :: "r"(mbar) : "memory");
    }
    __syncthreads();

    if (tid == 0) {
        asm volatile("mbarrier.arrive.expect_tx.shared.b64 _, [%0], %1;"
                     :: "r"(mbar), "r"((uint32_t)(FEATS_BYTES + COORS_BYTES)) : "memory");
        const char* gf = (const char*)(feats + (size_t)b * N_FIXED * NS);
        const char* gc = (const char*)(coors + (size_t)b * N_FIXED * 3);
        asm volatile(
            "cp.async.bulk.shared::cta.global.mbarrier::complete_tx::bytes "
            "[%0], [%1], %2, [%3];"
            :: "r"(smem_u32(s_feats)), "l"(gf), "r"((uint32_t)FEATS_BYTES), "r"(mbar)
            : "memory");
        asm volatile(
            "cp.async.bulk.shared::cta.global.mbarrier::complete_tx::bytes "
            "[%0], [%1], %2, [%3];"
            :: "r"(smem_u32(s_coors)), "l"(gc), "r"((uint32_t)COORS_BYTES), "r"(mbar)
            : "memory");
    }

    // Broadcast TP weights while the copies are in flight.
    float w[NS];
#pragma unroll
    for (int i = 0; i < NS; i++) w[i] = __ldg(&W_tp[i]);

    mbar_wait0(mbar);

    // Thread tid owns 4 consecutive nodes; all reads from conflict-free smem.
    float ax = 0.f, ay = 0.f, az = 0.f;
    {
        const float4* f4 = reinterpret_cast<const float4*>(s_feats) + tid * 7;
        float4 ff4[7];
#pragma unroll
        for (int i = 0; i < 7; i++) ff4[i] = f4[i];
        const float4* c4 = reinterpret_cast<const float4*>(s_coors) + tid * 3;
        float4 cc4[3];
#pragma unroll
        for (int i = 0; i < 3; i++) cc4[i] = c4[i];

        const float* ff = reinterpret_cast<const float*>(ff4);
        const float* cc = reinterpret_cast<const float*>(cc4);
#pragma unroll
        for (int j = 0; j < 4; j++) {
            float s = 0.f;
#pragma unroll
            for (int i = 0; i < NS; i++) s = fmaf(ff[j * NS + i], w[i], s);
            ax = fmaf(s, cc[j * 3 + 0], ax);
            ay = fmaf(s, cc[j * 3 + 1], ay);
            az = fmaf(s, cc[j * 3 + 2], az);
        }
    }

#pragma unroll
    for (int o = 16; o > 0; o >>= 1) {
        ax += __shfl_down_sync(0xFFFFFFFFu, ax, o);
        ay += __shfl_down_sync(0xFFFFFFFFu, ay, o);
        az += __shfl_down_sync(0xFFFFFFFFu, az, o);
    }
    if (lane == 0) { sx[wid] = ax; sy[wid] = ay; sz[wid] = az; }
    __syncthreads();

    if (wid == 0) {
        float rx = (lane < 4) ? sx[lane] : 0.f;
        float ry = (lane < 4) ? sy[lane] : 0.f;
        float rz = (lane < 4) ? sz[lane] : 0.f;
#pragma unroll
        for (int o = 2; o > 0; o >>= 1) {
            rx += __shfl_down_sync(0xFFFFFFFFu, rx, o);
            ry += __shfl_down_sync(0xFFFFFFFFu, ry, o);
            rz += __shfl_down_sync(0xFFFFFFFFu, rz, o);
        }
        const float scale = 0.3779644730092272f / (float)N_FIXED;  // 1/sqrt(7)/N
        float g0 = __shfl_sync(0xFFFFFFFFu, rx, 0) * scale;
        float g1 = __shfl_sync(0xFFFFFFFFu, ry, 0) * scale;
        float g2 = __shfl_sync(0xFFFFFFFFu, rz, 0) * scale;

        // MLP: out = W2 @ relu(W1 @ g + b1) + b2 ; each lane owns 4 hidden units.
        float o0 = 0.f, o1 = 0.f, o2 = 0.f;
#pragma unroll
        for (int r = 0; r < HID / 32; r++) {
            int j = lane + r * 32;
            float h = fmaf(W1[j * 3 + 0], g0,
                      fmaf(W1[j * 3 + 1], g1,
                      fmaf(W1[j * 3 + 2], g2, b1[j])));
            h = fmaxf(h, 0.f);
            o0 = fmaf(W2[0 * HID + j], h, o0);
            o1 = fmaf(W2[1 * HID + j], h, o1);
            o2 = fmaf(W2[2 * HID + j], h, o2);
        }
#pragma unroll
        for (int o = 16; o > 0; o >>= 1) {
            o0 += __shfl_down_sync(0xFFFFFFFFu, o0, o);
            o1 += __shfl_down_sync(0xFFFFFFFFu, o1, o);
            o2 += __shfl_down_sync(0xFFFFFFFFu, o2, o);
        }
        if (lane == 0) {
            out[b * 3 + 0] = o0 + b2[0];
            out[b * 3 + 1] = o1 + b2[1];
            out[b * 3 + 2] = o2 + b2[2];
        }
    }
}

// ---------- generic fallback (any N) ----------
__global__ __launch_bounds__(THREADS)
void dipole_ldg_kernel(const float* __restrict__ feats,
                       const float* __restrict__ coors,
                       const float* __restrict__ W_tp,
                       const float* __restrict__ W1,
                       const float* __restrict__ b1,
                       const float* __restrict__ W2,
                       const float* __restrict__ b2,
                       float* __restrict__ out,
                       int N)
{
    const int b    = blockIdx.x;
    const int tid  = threadIdx.x;
    const int lane = tid & 31;
    const int wid  = tid >> 5;
    float w[NS];
#pragma unroll
    for (int i = 0; i < NS; i++) w[i] = __ldg(&W_tp[i]);
    const float* fb = feats + (size_t)b * N * NS;
    const float* cb = coors + (size_t)b * N * 3;
    float ax = 0.f, ay = 0.f, az = 0.f;
    for (int n = tid; n < N; n += THREADS) {
        const float* fr = fb + (size_t)n * NS;
        float s = 0.f;
#pragma unroll
        for (int i = 0; i < NS; i++) s = fmaf(fr[i], w[i], s);
        const float* cr = cb + (size_t)n * 3;
        ax = fmaf(s, cr[0], ax);
        ay = fmaf(s, cr[1], ay);
        az = fmaf(s, cr[2], az);
    }
#pragma unroll
    for (int o = 16; o > 0; o >>= 1) {
        ax += __shfl_down_sync(0xFFFFFFFFu, ax, o);
        ay += __shfl_down_sync(0xFFFFFFFFu, ay, o);
        az += __shfl_down_sync(0xFFFFFFFFu, az, o);
    }
    __shared__ float sx[4], sy[4], sz[4];
    if (lane == 0) { sx[wid] = ax; sy[wid] = ay; sz[wid] = az; }
    __syncthreads();
    if (wid == 0) {
        float rx = (lane < 4) ? sx[lane] : 0.f;
        float ry = (lane < 4) ? sy[lane] : 0.f;
        float rz = (lane < 4) ? sz[lane] : 0.f;
#pragma unroll
        for (int o = 2; o > 0; o >>= 1) {
            rx += __shfl_down_sync(0xFFFFFFFFu, rx, o);
            ry += __shfl_down_sync(0xFFFFFFFFu, ry, o);
            rz += __shfl_down_sync(0xFFFFFFFFu, rz, o);
        }
        const float scale = 0.3779644730092272f / (float)N;
        float g0 = __shfl_sync(0xFFFFFFFFu, rx, 0) * scale;
        float g1 = __shfl_sync(0xFFFFFFFFu, ry, 0) * scale;
        float g2 = __shfl_sync(0xFFFFFFFFu, rz, 0) * scale;
        float o0 = 0.f, o1 = 0.f, o2 = 0.f;
#pragma unroll
        for (int r = 0; r < HID / 32; r++) {
            int j = lane + r * 32;
            float h = fmaf(W1[j * 3 + 0], g0,
                      fmaf(W1[j * 3 + 1], g1,
                      fmaf(W1[j * 3 + 2], g2, b1[j])));
            h = fmaxf(h, 0.f);
            o0 = fmaf(W2[0 * HID + j], h, o0);
            o1 = fmaf(W2[1 * HID + j], h, o1);
            o2 = fmaf(W2[2 * HID + j], h, o2);
        }
#pragma unroll
        for (int o = 16; o > 0; o >>= 1) {
            o0 += __shfl_down_sync(0xFFFFFFFFu, o0, o);
            o1 += __shfl_down_sync(0xFFFFFFFFu, o1, o);
            o2 += __shfl_down_sync(0xFFFFFFFFu, o2, o);
        }
        if (lane == 0) {
            out[b * 3 + 0] = o0 + b2[0];
            out[b * 3 + 1] = o1 + b2[1];
            out[b * 3 + 2] = o2 + b2[2];
        }
    }
}

extern "C" void kernel_launch(void* const* d_in, const int* in_sizes, int n_in,
                              void* d_out, int out_size)
{
    const float* feats = (const float*)d_in[0];
    const float* coors = (const float*)d_in[1];
    // d_in[2] = adj_mat, intentionally unused
    const float* W_tp  = (const float*)d_in[3];
    const float* W1    = (const float*)d_in[4];
    const float* b1    = (const float*)d_in[5];
    const float* W2    = (const float*)d_in[6];
    const float* b2    = (const float*)d_in[7];
    float* out = (float*)d_out;

    const int B = out_size / 3;           // output [B,3]
    const int N = in_sizes[1] / (B * 3);  // coors [B,N,3]

    if (N == N_FIXED) {
        dipole_final_kernel<<<B, THREADS>>>(feats, coors, W_tp, W1, b1, W2, b2, out);
    } else {
        dipole_ldg_kernel<<<B, THREADS>>>(feats, coors, W_tp, W1, b1, W2, b2, out, N);
    }
}